// round 13
// baseline (speedup 1.0000x reference)
#include <cuda_runtime.h>
#include <cstdint>
#include <mma.h>
#include <math.h>

using namespace nvcuda;

#define NE 8
#define NT 2048
#define NH 2048
#define NI 4096
#define TWO_I 8192
#define NSLOT (2*NT)

// Does this compilation pass support tcgen05 (arch- or family-specific sm_100/103)?
#if defined(__CUDA_ARCH__) && ( defined(__CUDA_ARCH_FEAT_SM103_ALL) || defined(__CUDA_ARCH_FEAT_SM100_ALL) \
    || (defined(__CUDA_ARCH_SPECIFIC__)        && (__CUDA_ARCH_SPECIFIC__ == 1000        || __CUDA_ARCH_SPECIFIC__ == 1010        || __CUDA_ARCH_SPECIFIC__ == 1030)) \
    || (defined(__CUDA_ARCH_FAMILY_SPECIFIC__) && (__CUDA_ARCH_FAMILY_SPECIFIC__ == 1000 || __CUDA_ARCH_FAMILY_SPECIFIC__ == 1030)) )
#define TC5 1
#else
#define TC5 0
#endif

// ---------------- scratch (device globals; no allocation APIs) ----------------
__device__ int   g_cnt[NE];
__device__ int   g_rows[NE * NT];
__device__ float g_gw[NSLOT];
__device__ float g_xr[(size_t)NT * NH];       // RNA-rounded copy of x (16MB)
__device__ float g_h [(size_t)NSLOT * TWO_I];
__device__ float g_i [(size_t)NSLOT * NI];    // silu output, RNA-rounded

// ---------------- ptx helpers ----------------
__device__ __forceinline__ unsigned smem_u32(const void* p) {
    return (unsigned)__cvta_generic_to_shared(p);
}
__device__ __forceinline__ void cpa16p(unsigned dst, const float* src, bool pred) {
    int sz = pred ? 16 : 0;
    asm volatile("cp.async.cg.shared.global [%0], [%1], 16, %2;\n" :: "r"(dst), "l"(src), "r"(sz));
}
__device__ __forceinline__ void cp_commit() { asm volatile("cp.async.commit_group;\n"); }
__device__ __forceinline__ void cp_wait0()  { asm volatile("cp.async.wait_group 0;\n"); }
__device__ __forceinline__ void cp_wait1()  { asm volatile("cp.async.wait_group 1;\n"); }

#if TC5
__device__ __forceinline__ void mbar_init(unsigned addr, unsigned cnt) {
    asm volatile("mbarrier.init.shared.b64 [%0], %1;" :: "r"(addr), "r"(cnt) : "memory");
}
__device__ __forceinline__ void mbar_wait(unsigned addr, unsigned parity) {
    asm volatile("{\n\t.reg .pred P;\n"
                 "W_%=:\n\t"
                 "mbarrier.try_wait.parity.acquire.cta.shared::cta.b64 P, [%0], %1, 0x989680;\n\t"
                 "@!P bra W_%=;\n\t}"
                 :: "r"(addr), "r"(parity) : "memory");
}
__device__ __forceinline__ void tm_alloc(unsigned smem_dst, unsigned ncols) {
    asm volatile("tcgen05.alloc.cta_group::1.sync.aligned.shared::cta.b32 [%0], %1;"
                 :: "r"(smem_dst), "r"(ncols) : "memory");
}
__device__ __forceinline__ void tm_relinq() {
    asm volatile("tcgen05.relinquish_alloc_permit.cta_group::1.sync.aligned;");
}
__device__ __forceinline__ void tm_dealloc(unsigned tmem, unsigned ncols) {
    asm volatile("tcgen05.dealloc.cta_group::1.sync.aligned.b32 %0, %1;" :: "r"(tmem), "r"(ncols));
}
__device__ __forceinline__ void mma_tf32_ss(unsigned d_tmem, unsigned long long a_desc,
                                            unsigned long long b_desc, unsigned idesc, bool accum) {
    unsigned en = accum ? 1u : 0u;
    asm volatile("{\n\t.reg .pred p;\n\t"
                 "setp.ne.u32 p, %5, 0;\n\t"
                 "tcgen05.mma.cta_group::1.kind::tf32 [%0], %1, %2, %3, {%4, %4, %4, %4}, p;\n\t}"
                 :: "r"(d_tmem), "l"(a_desc), "l"(b_desc), "r"(idesc), "r"(0u), "r"(en) : "memory");
}
__device__ __forceinline__ void tm_commit(unsigned mbar_addr) {
    asm volatile("tcgen05.commit.cta_group::1.mbarrier::arrive::one.shared::cluster.b64 [%0];"
                 :: "r"(mbar_addr) : "memory");
}
__device__ __forceinline__ void fence_async_shared() {
    asm volatile("fence.proxy.async.shared::cta;" ::: "memory");
}
__device__ __forceinline__ void tm_fence_after() {
    asm volatile("tcgen05.fence::after_thread_sync;" ::: "memory");
}
__device__ __forceinline__ void tm_wait_ld() {
    asm volatile("tcgen05.wait::ld.sync.aligned;" ::: "memory");
}
__device__ __forceinline__ void ldtm32(unsigned* r, unsigned tmem) {
    asm volatile("tcgen05.ld.sync.aligned.32x32b.x32.b32 "
        "{%0, %1, %2, %3, %4, %5, %6, %7, %8, %9, %10, %11, %12, %13, %14, %15, "
        " %16, %17, %18, %19, %20, %21, %22, %23, %24, %25, %26, %27, %28, %29, %30, %31}, [%32];"
        : "=r"(r[0]), "=r"(r[1]), "=r"(r[2]), "=r"(r[3]), "=r"(r[4]), "=r"(r[5]), "=r"(r[6]), "=r"(r[7]),
          "=r"(r[8]), "=r"(r[9]), "=r"(r[10]), "=r"(r[11]), "=r"(r[12]), "=r"(r[13]), "=r"(r[14]), "=r"(r[15]),
          "=r"(r[16]), "=r"(r[17]), "=r"(r[18]), "=r"(r[19]), "=r"(r[20]), "=r"(r[21]), "=r"(r[22]), "=r"(r[23]),
          "=r"(r[24]), "=r"(r[25]), "=r"(r[26]), "=r"(r[27]), "=r"(r[28]), "=r"(r[29]), "=r"(r[30]), "=r"(r[31])
        : "r"(tmem));
}
#endif // TC5

#define SWZ(o) ((o) ^ (((o) >> 3) & 0x70))
static constexpr unsigned long long SMEM_DESC_BASE_SW128 =
    (2ULL << 61) | (1ULL << 46) | (64ULL << 32) | (1ULL << 16);
// idesc: dtype=F32 (1<<4), atype=TF32 (2<<7), btype=TF32 (2<<10), N=128 (16<<17), M=128 (8<<24)
static constexpr unsigned IDESC_TF32 = (1u << 4) | (2u << 7) | (2u << 10) | (16u << 17) | (8u << 24);

__device__ __forceinline__ float4 cvt4(float4 v) {
    v.x = wmma::__float_to_tf32(v.x);
    v.y = wmma::__float_to_tf32(v.y);
    v.z = wmma::__float_to_tf32(v.z);
    v.w = wmma::__float_to_tf32(v.w);
    return v;
}

// ---------------- misc kernels ----------------
__global__ void k_zero_cnt() { if (threadIdx.x < NE) g_cnt[threadIdx.x] = 0; }

// RNA-rounded copy of x -> g_xr (GEMM1's A source for cp.async)
__global__ void k_round_x(const float* __restrict__ x) {
    size_t idx = (size_t)blockIdx.x * blockDim.x + threadIdx.x;
    if (idx >= (size_t)NT * NH / 4) return;
    *(float4*)(g_xr + idx * 4) = cvt4(*(const float4*)(x + idx * 4));
}

// ---------------- router + sparsemixer ----------------
__global__ void k_router(const float* __restrict__ x, const float* __restrict__ gw) {
    int t = blockIdx.x;
    int warp = threadIdx.x >> 5, lane = threadIdx.x & 31;
    __shared__ float s[NE];
    const float* xr = x + (size_t)t * NH;
    const float* we = gw + (size_t)warp * NH;
    float acc = 0.f;
    for (int k = lane; k < NH; k += 32) acc += xr[k] * we[k];
    #pragma unroll
    for (int o = 16; o; o >>= 1) acc += __shfl_xor_sync(0xffffffffu, acc, o);
    if (lane == 0) s[warp] = acc;
    __syncthreads();
    if (threadIdx.x == 0) {
        float sc[NE];
        #pragma unroll
        for (int e = 0; e < NE; e++) sc[e] = s[e];

        float mx1 = -INFINITY; int i1 = 0;
        #pragma unroll
        for (int e = 0; e < NE; e++) if (sc[e] > mx1) { mx1 = sc[e]; i1 = e; }
        float sum1 = 0.f;
        #pragma unroll
        for (int e = 0; e < NE; e++) {
            float f = fmaxf(fabsf(sc[e]), mx1);
            if (!(((mx1 - sc[e]) / f) > 0.02f)) sum1 += expf(sc[e] - mx1);
        }
        float g1 = 1.f / sum1;

        float mx2 = -INFINITY; int i2 = 0;
        #pragma unroll
        for (int e = 0; e < NE; e++) if (e != i1 && sc[e] > mx2) { mx2 = sc[e]; i2 = e; }
        float sum2 = 0.f;
        #pragma unroll
        for (int e = 0; e < NE; e++) {
            if (e == i1) continue;
            float f = fmaxf(fabsf(sc[e]), mx2);
            if (!(((mx2 - sc[e]) / f) > 0.02f)) sum2 += expf(sc[e] - mx2);
        }
        float g2 = 1.f / sum2;

        int p1 = atomicAdd(&g_cnt[i1], 1);
        g_rows[i1 * NT + p1] = 2 * t;
        g_gw[2 * t] = g1;
        int p2 = atomicAdd(&g_cnt[i2], 1);
        g_rows[i2 * NT + p2] = 2 * t + 1;
        g_gw[2 * t + 1] = g2;
    }
}

// ---------------- grouped GEMM: tcgen05 tf32 SS, M=256 per CTA (2 D tiles share B) ----------------
// MODE 1: A = g_xr (row = rid>>1, K=NH), B = ws[e] [8192,2048] -> g_h rows
// MODE 2: A = g_i  (row = rid,    K=NI), B = w2s[e] [2048,4096] -> atomicAdd(out) * gate
constexpr int BM = 256, BN = 128;
constexpr int TILE = 16384;                   // one 128x128B tile
// smem (1024-aligned base): A(s,t) at (s*2+t)*16K, s=0..2, t=0..1 (96KB); B(b) at 96K + b*16K (32KB)
constexpr int BOFF = 98304;
constexpr int SMEM_BYTES = 128 * 1024 + 1024; // 132096; 1 CTA/SM; covers wmma fallback (~68KB)
constexpr int TM_COLS = 256;                  // D tile0 @ 0, D tile1 @ 128
// wmma fallback constants (round-1 config, per 128-row sub-tile)
constexpr int FBK = 16, KPAD = 24, CLD = BN + 4;

template<int MODE>
__global__ void __launch_bounds__(256) k_gemm(const float* __restrict__ Aarg,
                                              const float* __restrict__ Barg,
                                              float* __restrict__ Carg) {
    constexpr int K = (MODE == 1) ? NH : NI;
    constexpr int N = (MODE == 1) ? TWO_I : NH;

    int e = blockIdx.z;
    int cnt = g_cnt[e];
    int m0 = blockIdx.x * BM;
    if (m0 >= cnt) return;
    int n0 = blockIdx.y * BN;

    extern __shared__ float smem[];
    __shared__ int rowids[BM];

    int tid = threadIdx.x;
    rowids[tid] = (m0 + tid < cnt) ? g_rows[e * NT + m0 + tid] : -1;

    const float* A = (MODE == 1) ? (const float*)g_xr : (const float*)g_i;
    const float* Bexp = Barg + (size_t)e * N * K;

#if TC5
    // ================= tcgen05: A cp.async 3-stage x 2 tiles, B reg-RNA 2-stage =================
    constexpr int NSTAGE = K / 32;
    __shared__ unsigned tmem_ptr_s;
    __shared__ __align__(8) unsigned long long mbar[2];

    int wid = tid >> 5, lane = tid & 31;
    if (wid == 0) { tm_alloc(smem_u32(&tmem_ptr_s), TM_COLS); tm_relinq(); }
    if (tid == 0) { mbar_init(smem_u32(&mbar[0]), 1); mbar_init(smem_u32(&mbar[1]), 1); }
    __syncthreads();
    unsigned tmem_d = tmem_ptr_s;

    // 1024-align dynamic smem
    unsigned raw = smem_u32(smem);
    unsigned base = (raw + 1023u) & ~1023u;
    char* smc = (char*)smem + (base - raw);

    unsigned mb[2] = { smem_u32(&mbar[0]), smem_u32(&mbar[1]) };
    unsigned ph[2] = { 0u, 0u };

    // A loader: thread -> row tid (tile tid>>7, local row tid&127), 8 x 16B per stage
    int tA = tid >> 7;
    int rA = tid & 127;
    int rid_a = rowids[tid];
    bool av = (rid_a >= 0);
    const float* abase = A + (size_t)(av ? ((MODE == 1) ? (rid_a >> 1) : rid_a) : 0) * K;
    unsigned swoA[8];
    #pragma unroll
    for (int j = 0; j < 8; j++) swoA[j] = SWZ((unsigned)(rA * 128 + j * 16));

    // B loader: thread -> row tid>>1, half tid&1 -> 4 x 16B chunks (LDG -> RNA cvt -> STS)
    int rowB = tid >> 1;
    int halfB = tid & 1;
    const float* bbase = Bexp + (size_t)(n0 + rowB) * K + halfB * 16;
    unsigned swoB[4];
    #pragma unroll
    for (int j = 0; j < 4; j++) swoB[j] = SWZ((unsigned)(rowB * 128 + (halfB * 4 + j) * 16));

    float4 rb[4];
    // prologue: issue A(0) cp.async (both tiles), load B(0) into regs
    {
        unsigned ao = (unsigned)(0 * 2 + tA) * TILE;
        #pragma unroll
        for (int j = 0; j < 8; j++) cpa16p(base + ao + swoA[j], abase + j * 4, av);
        cp_commit();
        #pragma unroll
        for (int j = 0; j < 4; j++) rb[j] = *(const float4*)(bbase + j * 4);
    }

    #pragma unroll 1
    for (int i = 0; i < NSTAGE; i++) {
        int b = i & 1;
        int s = i % 3;
        if (i >= 2) { mbar_wait(mb[b], ph[b]); ph[b] ^= 1u; }   // MMA(i-2) done

        // STS pre-rounded B stage i
        unsigned boffb = (unsigned)BOFF + (unsigned)b * TILE;
        #pragma unroll
        for (int j = 0; j < 4; j++) *(float4*)(smc + boffb + swoB[j]) = cvt4(rb[j]);

        if (i + 1 < NSTAGE) {
            // issue A(i+1) into stage-slot (i+1)%3 (last read by MMA(i-2), waited above)
            unsigned ao = (unsigned)(((i + 1) % 3) * 2 + tA) * TILE;
            const float* ap = abase + (i + 1) * 32;
            #pragma unroll
            for (int j = 0; j < 8; j++) cpa16p(base + ao + swoA[j], ap + j * 4, av);
            cp_commit();
            // prefetch B(i+1) into regs
            const float* bp = bbase + (i + 1) * 32;
            #pragma unroll
            for (int j = 0; j < 4; j++) rb[j] = *(const float4*)(bp + j * 4);
            cp_wait1();   // A(i) landed
        } else {
            cp_wait0();
        }
        __syncthreads();
        fence_async_shared();

        if (tid == 0) {
            unsigned long long a0 = SMEM_DESC_BASE_SW128 |
                (((unsigned long long)((base + (unsigned)(s * 2 + 0) * TILE) >> 4)) & 0x3FFF);
            unsigned long long a1 = SMEM_DESC_BASE_SW128 |
                (((unsigned long long)((base + (unsigned)(s * 2 + 1) * TILE) >> 4)) & 0x3FFF);
            unsigned long long bd = SMEM_DESC_BASE_SW128 |
                (((unsigned long long)((base + boffb) >> 4)) & 0x3FFF);
            bool acc0 = (i > 0);
            #pragma unroll
            for (int k = 0; k < 4; k++) {
                mma_tf32_ss(tmem_d,       a0 + k * 2, bd + k * 2, IDESC_TF32, acc0 || (k > 0));
                mma_tf32_ss(tmem_d + 128, a1 + k * 2, bd + k * 2, IDESC_TF32, acc0 || (k > 0));
            }
            tm_commit(mb[b]);
        }
    }

    int bl = (NSTAGE - 1) & 1;
    mbar_wait(mb[bl], ph[bl]);
    tm_fence_after();

    // epilogue: per tile t: warp w -> rows t*128 + (w&3)*32+lane, cols (w>>2)*64 (2 halves)
    int colg = (wid >> 2) * 64;
    #pragma unroll
    for (int t = 0; t < 2; t++) {
        int m = t * 128 + (wid & 3) * 32 + lane;
        int rid = rowids[m];
        #pragma unroll
        for (int hf = 0; hf < 2; hf++) {
            unsigned r[32];
            ldtm32(r, tmem_d + t * 128 + colg + hf * 32);
            tm_wait_ld();
            if (rid >= 0) {
                int nb = n0 + colg + hf * 32;
                if (MODE == 1) {
                    float* dst = g_h + (size_t)rid * TWO_I + nb;
                    #pragma unroll
                    for (int c = 0; c < 32; c += 4) {
                        float4 v = make_float4(__uint_as_float(r[c]), __uint_as_float(r[c+1]),
                                               __uint_as_float(r[c+2]), __uint_as_float(r[c+3]));
                        *(float4*)(dst + c) = v;
                    }
                } else {
                    float g = g_gw[rid];
                    float* dst = Carg + (size_t)(rid >> 1) * NH + nb;
                    #pragma unroll
                    for (int c = 0; c < 32; c++)
                        atomicAdd(dst + c, g * __uint_as_float(r[c]));
                }
            }
        }
    }
    __syncthreads();
    if (wid == 0) tm_dealloc(tmem_d, TM_COLS);

#else
    // ================= wmma tf32 fallback (round-1 body, two 128-row sub-tiles) =================
    __syncthreads();
    int warp = tid >> 5;
    int wm = warp & 1;
    int wn = warp >> 1;

    for (int t = 0; t < 2; t++) {
        int mb0 = t * 128;

        wmma::fragment<wmma::accumulator, 16, 16, 8, float> acc[4][2];
        #pragma unroll
        for (int fm = 0; fm < 4; fm++)
            #pragma unroll
            for (int fn = 0; fn < 2; fn++)
                wmma::fill_fragment(acc[fm][fn], 0.f);

        int lr = tid >> 2, lq = tid & 3;
        int r0 = rowids[mb0 + lr], r1 = rowids[mb0 + lr + 64];
        bool v0 = (r0 >= 0), v1 = (r1 >= 0);
        size_t ar0 = (size_t)(v0 ? ((MODE == 1) ? (r0 >> 1) : r0) : 0) * K;
        size_t ar1 = (size_t)(v1 ? ((MODE == 1) ? (r1 >> 1) : r1) : 0) * K;
        const float4 zero4 = make_float4(0.f, 0.f, 0.f, 0.f);
        float* As = smem;
        float* Bs = smem + 128 * KPAD;

        for (int kb = 0; kb < K; kb += FBK) {
            float4 av0 = v0 ? *(const float4*)(A + ar0 + kb + lq * 4) : zero4;
            float4 av1 = v1 ? *(const float4*)(A + ar1 + kb + lq * 4) : zero4;
            float4 bv0 = *(const float4*)(Bexp + (size_t)(n0 + lr) * K + kb + lq * 4);
            float4 bv1 = *(const float4*)(Bexp + (size_t)(n0 + lr + 64) * K + kb + lq * 4);
            *(float4*)(As + lr * KPAD + lq * 4) = av0;
            *(float4*)(As + (lr + 64) * KPAD + lq * 4) = av1;
            *(float4*)(Bs + lr * KPAD + lq * 4) = bv0;
            *(float4*)(Bs + (lr + 64) * KPAD + lq * 4) = bv1;
            __syncthreads();

            #pragma unroll
            for (int kk = 0; kk < FBK; kk += 8) {
                wmma::fragment<wmma::matrix_a, 16, 16, 8, wmma::precision::tf32, wmma::row_major> af[4];
                wmma::fragment<wmma::matrix_b, 16, 16, 8, wmma::precision::tf32, wmma::col_major> bf[2];
                #pragma unroll
                for (int fm = 0; fm < 4; fm++) {
                    wmma::load_matrix_sync(af[fm], As + (wm * 64 + fm * 16) * KPAD + kk, KPAD);
                    #pragma unroll
                    for (int u = 0; u < af[fm].num_elements; u++)
                        af[fm].x[u] = wmma::__float_to_tf32(af[fm].x[u]);
                }
                #pragma unroll
                for (int fn = 0; fn < 2; fn++) {
                    wmma::load_matrix_sync(bf[fn], Bs + (wn * 32 + fn * 16) * KPAD + kk, KPAD);
                    #pragma unroll
                    for (int u = 0; u < bf[fn].num_elements; u++)
                        bf[fn].x[u] = wmma::__float_to_tf32(bf[fn].x[u]);
                }
                #pragma unroll
                for (int fm = 0; fm < 4; fm++)
                    #pragma unroll
                    for (int fn = 0; fn < 2; fn++)
                        wmma::mma_sync(acc[fm][fn], af[fm], bf[fn], acc[fm][fn]);
            }
            __syncthreads();
        }

        float* Cs = smem;
        #pragma unroll
        for (int fm = 0; fm < 4; fm++)
            #pragma unroll
            for (int fn = 0; fn < 2; fn++)
                wmma::store_matrix_sync(Cs + (size_t)(wm * 64 + fm * 16) * CLD + wn * 32 + fn * 16,
                                        acc[fm][fn], CLD, wmma::mem_row_major);
        __syncthreads();

        int r = tid >> 1;
        int ch = (tid & 1) * 64;
        int rid = rowids[mb0 + r];
        if (rid >= 0) {
            const float* src = Cs + (size_t)r * CLD + ch;
            if (MODE == 1) {
                float* dst = g_h + (size_t)rid * TWO_I + n0 + ch;
                #pragma unroll
                for (int c = 0; c < 64; c += 4)
                    *(float4*)(dst + c) = *(const float4*)(src + c);
            } else {
                float g = g_gw[rid];
                float* dst = Carg + (size_t)(rid >> 1) * NH + n0 + ch;
                #pragma unroll
                for (int c = 0; c < 64; c++)
                    atomicAdd(dst + c, g * src[c]);
            }
        }
        __syncthreads();
    }
#endif
}

// ---------------- silu(gate) * up, output RNA-rounded (GEMM2's A needs no further cvt) ----------------
__global__ void k_silu() {
    size_t idx = (size_t)blockIdx.x * blockDim.x + threadIdx.x;
    size_t total = (size_t)NSLOT * NI / 4;
    if (idx >= total) return;
    size_t r = idx / (NI / 4);
    size_t c = (idx % (NI / 4)) * 4;
    float4 gv = *(const float4*)(g_h + r * TWO_I + c);
    float4 uv = *(const float4*)(g_h + r * TWO_I + NI + c);
    float4 o;
    o.x = gv.x / (1.f + expf(-gv.x)) * uv.x;
    o.y = gv.y / (1.f + expf(-gv.y)) * uv.y;
    o.z = gv.z / (1.f + expf(-gv.z)) * uv.z;
    o.w = gv.w / (1.f + expf(-gv.w)) * uv.w;
    *(float4*)(g_i + r * NI + c) = cvt4(o);
}

// ---------------- launch ----------------
extern "C" void kernel_launch(void* const* d_in, const int* in_sizes, int n_in,
                              void* d_out, int out_size) {
    const float* x     = (const float*)d_in[0];
    const float* gatew = (const float*)d_in[1];
    const float* ws    = (const float*)d_in[2];
    const float* w2s   = (const float*)d_in[3];
    float* out = (float*)d_out;

    cudaFuncSetAttribute((const void*)k_gemm<1>, cudaFuncAttributeMaxDynamicSharedMemorySize, SMEM_BYTES);
    cudaFuncSetAttribute((const void*)k_gemm<2>, cudaFuncAttributeMaxDynamicSharedMemorySize, SMEM_BYTES);

    cudaMemsetAsync(d_out, 0, (size_t)out_size * sizeof(float), 0);
    k_zero_cnt<<<1, 32>>>();
    k_round_x<<<(int)(((size_t)NT * NH / 4 + 255) / 256), 256>>>(x);
    k_router<<<NT, 256>>>(x, gatew);
    // launch #5 (incl. memset) = k_gemm<1> -> ncu -s 5 profiles it

    dim3 g1(NT / BM, TWO_I / BN, NE);
    k_gemm<1><<<g1, 256, SMEM_BYTES>>>(nullptr, ws, nullptr);

    k_silu<<<(int)(((size_t)NSLOT * NI / 4 + 255) / 256), 256>>>();

    dim3 g2(NT / BM, NH / BN, NE);
    k_gemm<2><<<g2, 256, SMEM_BYTES>>>(nullptr, w2s, out);
}

// round 14
// speedup vs baseline: 1.3289x; 1.3289x over previous
#include <cuda_runtime.h>
#include <cstdint>
#include <mma.h>
#include <math.h>

using namespace nvcuda;

#define NE 8
#define NT 2048
#define NH 2048
#define NI 4096
#define TWO_I 8192
#define NSLOT (2*NT)

// Does this compilation pass support tcgen05 (arch- or family-specific sm_100/103)?
#if defined(__CUDA_ARCH__) && ( defined(__CUDA_ARCH_FEAT_SM103_ALL) || defined(__CUDA_ARCH_FEAT_SM100_ALL) \
    || (defined(__CUDA_ARCH_SPECIFIC__)        && (__CUDA_ARCH_SPECIFIC__ == 1000        || __CUDA_ARCH_SPECIFIC__ == 1010        || __CUDA_ARCH_SPECIFIC__ == 1030)) \
    || (defined(__CUDA_ARCH_FAMILY_SPECIFIC__) && (__CUDA_ARCH_FAMILY_SPECIFIC__ == 1000 || __CUDA_ARCH_FAMILY_SPECIFIC__ == 1030)) )
#define TC5 1
#else
#define TC5 0
#endif

// ---------------- scratch (device globals; no allocation APIs) ----------------
__device__ int   g_cnt[NE];
__device__ int   g_rows[NE * NT];
__device__ float g_gw[NSLOT];
__device__ float g_xr[(size_t)NT * NH];       // RNA-rounded copy of x (16MB)
__device__ float g_i [(size_t)NSLOT * NI];    // silu(gate)*up, RNA-rounded (written by GEMM1 epilogue)

// ---------------- ptx helpers ----------------
__device__ __forceinline__ unsigned smem_u32(const void* p) {
    return (unsigned)__cvta_generic_to_shared(p);
}
__device__ __forceinline__ void cpa16p(unsigned dst, const float* src, bool pred) {
    int sz = pred ? 16 : 0;
    asm volatile("cp.async.cg.shared.global [%0], [%1], 16, %2;\n" :: "r"(dst), "l"(src), "r"(sz));
}
__device__ __forceinline__ void cp_commit() { asm volatile("cp.async.commit_group;\n"); }
__device__ __forceinline__ void cp_wait0()  { asm volatile("cp.async.wait_group 0;\n"); }
__device__ __forceinline__ void cp_wait1()  { asm volatile("cp.async.wait_group 1;\n"); }

#if TC5
__device__ __forceinline__ void mbar_init(unsigned addr, unsigned cnt) {
    asm volatile("mbarrier.init.shared.b64 [%0], %1;" :: "r"(addr), "r"(cnt) : "memory");
}
__device__ __forceinline__ void mbar_wait(unsigned addr, unsigned parity) {
    asm volatile("{\n\t.reg .pred P;\n"
                 "W_%=:\n\t"
                 "mbarrier.try_wait.parity.acquire.cta.shared::cta.b64 P, [%0], %1, 0x989680;\n\t"
                 "@!P bra W_%=;\n\t}"
                 :: "r"(addr), "r"(parity) : "memory");
}
__device__ __forceinline__ void tm_alloc(unsigned smem_dst, unsigned ncols) {
    asm volatile("tcgen05.alloc.cta_group::1.sync.aligned.shared::cta.b32 [%0], %1;"
                 :: "r"(smem_dst), "r"(ncols) : "memory");
}
__device__ __forceinline__ void tm_relinq() {
    asm volatile("tcgen05.relinquish_alloc_permit.cta_group::1.sync.aligned;");
}
__device__ __forceinline__ void tm_dealloc(unsigned tmem, unsigned ncols) {
    asm volatile("tcgen05.dealloc.cta_group::1.sync.aligned.b32 %0, %1;" :: "r"(tmem), "r"(ncols));
}
__device__ __forceinline__ void mma_tf32_ss(unsigned d_tmem, unsigned long long a_desc,
                                            unsigned long long b_desc, unsigned idesc, bool accum) {
    unsigned en = accum ? 1u : 0u;
    asm volatile("{\n\t.reg .pred p;\n\t"
                 "setp.ne.u32 p, %5, 0;\n\t"
                 "tcgen05.mma.cta_group::1.kind::tf32 [%0], %1, %2, %3, {%4, %4, %4, %4}, p;\n\t}"
                 :: "r"(d_tmem), "l"(a_desc), "l"(b_desc), "r"(idesc), "r"(0u), "r"(en) : "memory");
}
__device__ __forceinline__ void tm_commit(unsigned mbar_addr) {
    asm volatile("tcgen05.commit.cta_group::1.mbarrier::arrive::one.shared::cluster.b64 [%0];"
                 :: "r"(mbar_addr) : "memory");
}
__device__ __forceinline__ void fence_async_shared() {
    asm volatile("fence.proxy.async.shared::cta;" ::: "memory");
}
__device__ __forceinline__ void tm_fence_after() {
    asm volatile("tcgen05.fence::after_thread_sync;" ::: "memory");
}
__device__ __forceinline__ void tm_wait_ld() {
    asm volatile("tcgen05.wait::ld.sync.aligned;" ::: "memory");
}
__device__ __forceinline__ void ldtm32(unsigned* r, unsigned tmem) {
    asm volatile("tcgen05.ld.sync.aligned.32x32b.x32.b32 "
        "{%0, %1, %2, %3, %4, %5, %6, %7, %8, %9, %10, %11, %12, %13, %14, %15, "
        " %16, %17, %18, %19, %20, %21, %22, %23, %24, %25, %26, %27, %28, %29, %30, %31}, [%32];"
        : "=r"(r[0]), "=r"(r[1]), "=r"(r[2]), "=r"(r[3]), "=r"(r[4]), "=r"(r[5]), "=r"(r[6]), "=r"(r[7]),
          "=r"(r[8]), "=r"(r[9]), "=r"(r[10]), "=r"(r[11]), "=r"(r[12]), "=r"(r[13]), "=r"(r[14]), "=r"(r[15]),
          "=r"(r[16]), "=r"(r[17]), "=r"(r[18]), "=r"(r[19]), "=r"(r[20]), "=r"(r[21]), "=r"(r[22]), "=r"(r[23]),
          "=r"(r[24]), "=r"(r[25]), "=r"(r[26]), "=r"(r[27]), "=r"(r[28]), "=r"(r[29]), "=r"(r[30]), "=r"(r[31])
        : "r"(tmem));
}
#endif // TC5

#define SWZ(o) ((o) ^ (((o) >> 3) & 0x70))
static constexpr unsigned long long SMEM_DESC_BASE_SW128 =
    (2ULL << 61) | (1ULL << 46) | (64ULL << 32) | (1ULL << 16);
// idesc: dtype=F32 (1<<4), atype=TF32 (2<<7), btype=TF32 (2<<10), N=128 (16<<17), M=128 (8<<24)
static constexpr unsigned IDESC_TF32 = (1u << 4) | (2u << 7) | (2u << 10) | (16u << 17) | (8u << 24);

__device__ __forceinline__ float4 cvt4(float4 v) {
    v.x = wmma::__float_to_tf32(v.x);
    v.y = wmma::__float_to_tf32(v.y);
    v.z = wmma::__float_to_tf32(v.z);
    v.w = wmma::__float_to_tf32(v.w);
    return v;
}
__device__ __forceinline__ float silu_mul(float g, float u) {
    return g / (1.f + expf(-g)) * u;
}

// ---------------- misc kernels ----------------
__global__ void k_zero_cnt() { if (threadIdx.x < NE) g_cnt[threadIdx.x] = 0; }

// RNA-rounded copy of x -> g_xr (GEMM1's A source for cp.async)
__global__ void k_round_x(const float* __restrict__ x) {
    size_t idx = (size_t)blockIdx.x * blockDim.x + threadIdx.x;
    if (idx >= (size_t)NT * NH / 4) return;
    *(float4*)(g_xr + idx * 4) = cvt4(*(const float4*)(x + idx * 4));
}

// ---------------- router + sparsemixer ----------------
__global__ void k_router(const float* __restrict__ x, const float* __restrict__ gw) {
    int t = blockIdx.x;
    int warp = threadIdx.x >> 5, lane = threadIdx.x & 31;
    __shared__ float s[NE];
    const float* xr = x + (size_t)t * NH;
    const float* we = gw + (size_t)warp * NH;
    float acc = 0.f;
    for (int k = lane; k < NH; k += 32) acc += xr[k] * we[k];
    #pragma unroll
    for (int o = 16; o; o >>= 1) acc += __shfl_xor_sync(0xffffffffu, acc, o);
    if (lane == 0) s[warp] = acc;
    __syncthreads();
    if (threadIdx.x == 0) {
        float sc[NE];
        #pragma unroll
        for (int e = 0; e < NE; e++) sc[e] = s[e];

        float mx1 = -INFINITY; int i1 = 0;
        #pragma unroll
        for (int e = 0; e < NE; e++) if (sc[e] > mx1) { mx1 = sc[e]; i1 = e; }
        float sum1 = 0.f;
        #pragma unroll
        for (int e = 0; e < NE; e++) {
            float f = fmaxf(fabsf(sc[e]), mx1);
            if (!(((mx1 - sc[e]) / f) > 0.02f)) sum1 += expf(sc[e] - mx1);
        }
        float g1 = 1.f / sum1;

        float mx2 = -INFINITY; int i2 = 0;
        #pragma unroll
        for (int e = 0; e < NE; e++) if (e != i1 && sc[e] > mx2) { mx2 = sc[e]; i2 = e; }
        float sum2 = 0.f;
        #pragma unroll
        for (int e = 0; e < NE; e++) {
            if (e == i1) continue;
            float f = fmaxf(fabsf(sc[e]), mx2);
            if (!(((mx2 - sc[e]) / f) > 0.02f)) sum2 += expf(sc[e] - mx2);
        }
        float g2 = 1.f / sum2;

        int p1 = atomicAdd(&g_cnt[i1], 1);
        g_rows[i1 * NT + p1] = 2 * t;
        g_gw[2 * t] = g1;
        int p2 = atomicAdd(&g_cnt[i2], 1);
        g_rows[i2 * NT + p2] = 2 * t + 1;
        g_gw[2 * t + 1] = g2;
    }
}

// ---------------- grouped GEMM (round-12 config): tcgen05 tf32 SS 128x128, cp.async A, reg-RNA B ----------------
// MODE 1: A = g_xr (row = rid>>1, K=NH), B = ws[e] rows {gate n0g..+63} U {up NI+n0g..+63},
//         epilogue computes silu(gate)*up -> g_i[rid][n0g..+63] (fused, no g_h / k_silu)
// MODE 2: A = g_i  (row = rid,    K=NI), B = w2s[e] [2048,4096] -> atomicAdd(out) * gate
constexpr int BM = 128, BN = 128;
constexpr int STG = 16384;                    // one 128x128B tile
constexpr int BOFF = 65536;                   // A bufs 0..3 @ [0,64K); B bufs 0..1 @ [64K,96K)
constexpr int SMEM_BYTES = 96 * 1024 + 1024;  // 99328 -> 2 CTAs/SM
constexpr int TM_COLS = 128;
// wmma fallback constants
constexpr int FBK = 16, KPAD = 24, CLD = BN + 4;

template<int MODE>
__global__ void __launch_bounds__(256, 2) k_gemm(const float* __restrict__ Aarg,
                                                 const float* __restrict__ Barg,
                                                 float* __restrict__ Carg) {
    constexpr int K = (MODE == 1) ? NH : NI;
    constexpr int N = (MODE == 1) ? TWO_I : NH;

    int e = blockIdx.z;
    int cnt = g_cnt[e];
    int m0 = blockIdx.x * BM;
    if (m0 >= cnt) return;
    // MODE1: n-block = 64 gate cols (and their paired up rows). MODE2: 128 output cols.
    int n0g = blockIdx.y * 64;            // MODE1 g_i column base
    int n0 = blockIdx.y * BN;             // MODE2 output column base

    extern __shared__ float smem[];
    __shared__ int rowids[BM];

    int tid = threadIdx.x;
    if (tid < BM) rowids[tid] = (m0 + tid < cnt) ? g_rows[e * NT + m0 + tid] : -1;

    const float* A = (MODE == 1) ? (const float*)g_xr : (const float*)g_i;
    const float* Bexp = Barg + (size_t)e * N * K;

#if TC5
    // ================= tcgen05 tf32 SS: A cp.async (4 bufs), B reg-RNA (2 bufs) =================
    constexpr int NSTAGE = K / 32;
    __shared__ unsigned tmem_ptr_s;
    __shared__ __align__(8) unsigned long long mbar[2];

    int wid = tid >> 5, lane = tid & 31;
    if (wid == 0) { tm_alloc(smem_u32(&tmem_ptr_s), TM_COLS); tm_relinq(); }
    if (tid == 0) { mbar_init(smem_u32(&mbar[0]), 1); mbar_init(smem_u32(&mbar[1]), 1); }
    __syncthreads();
    unsigned tmem_d = tmem_ptr_s;

    // 1024-align dynamic smem
    unsigned raw = smem_u32(smem);
    unsigned base = (raw + 1023u) & ~1023u;
    char* smc = (char*)smem + (base - raw);

    unsigned mb[2] = { smem_u32(&mbar[0]), smem_u32(&mbar[1]) };
    unsigned ph[2] = { 0u, 0u };

    // loader mapping (both A and B): thread -> row tid>>1, half tid&1 -> 4x16B chunks
    int row = tid >> 1;
    int half = tid & 1;
    int rid_l = rowids[row];
    bool av = (rid_l >= 0);
    const float* abase = A + (size_t)(av ? ((MODE == 1) ? (rid_l >> 1) : rid_l) : 0) * K + half * 16;
    // B row: MODE1 pairs gate rows [n0g,n0g+64) at local 0..63 with up rows [NI+n0g,..) at 64..127
    int browg = (MODE == 1)
        ? ((row < 64) ? (n0g + row) : (NI + n0g + (row - 64)))
        : (n0 + row);
    const float* bbase = Bexp + (size_t)browg * K + half * 16;
    unsigned swo[4];
    #pragma unroll
    for (int j = 0; j < 4; j++) swo[j] = SWZ((unsigned)(row * 128 + (half * 4 + j) * 16));

    float4 rb[4];
    // prologue: issue A(0) cp.async, load B(0) into regs
    #pragma unroll
    for (int j = 0; j < 4; j++) cpa16p(base + 0 * STG + swo[j], abase + j * 4, av);
    cp_commit();
    #pragma unroll
    for (int j = 0; j < 4; j++) rb[j] = *(const float4*)(bbase + j * 4);

    #pragma unroll 1
    for (int i = 0; i < NSTAGE; i++) {
        int b = i & 1;
        if (i >= 2) { mbar_wait(mb[b], ph[b]); ph[b] ^= 1u; }   // MMA(i-2) done

        unsigned boffb = (unsigned)BOFF + (unsigned)b * STG;
        #pragma unroll
        for (int j = 0; j < 4; j++) *(float4*)(smc + boffb + swo[j]) = cvt4(rb[j]);

        if (i + 1 < NSTAGE) {
            unsigned ao = (unsigned)((i + 1) & 3) * STG;
            const float* ap = abase + (i + 1) * 32;
            #pragma unroll
            for (int j = 0; j < 4; j++) cpa16p(base + ao + swo[j], ap + j * 4, av);
            cp_commit();
            const float* bp = bbase + (i + 1) * 32;
            #pragma unroll
            for (int j = 0; j < 4; j++) rb[j] = *(const float4*)(bp + j * 4);
            cp_wait1();
        } else {
            cp_wait0();
        }
        __syncthreads();
        fence_async_shared();

        if (tid == 0) {
            unsigned long long ad = SMEM_DESC_BASE_SW128 |
                (((unsigned long long)((base + (unsigned)(i & 3) * STG) >> 4)) & 0x3FFF);
            unsigned long long bd = SMEM_DESC_BASE_SW128 |
                (((unsigned long long)((base + boffb) >> 4)) & 0x3FFF);
            #pragma unroll
            for (int k = 0; k < 4; k++)
                mma_tf32_ss(tmem_d, ad + k * 2, bd + k * 2, IDESC_TF32, (i > 0) || (k > 0));
            tm_commit(mb[b]);
        }
    }

    int bl = (NSTAGE - 1) & 1;
    mbar_wait(mb[bl], ph[bl]);
    tm_fence_after();

    if (MODE == 1) {
        // fused silu epilogue: warps 0-3 read gate cols [0,64) and up cols [64,128) for their rows
        if (wid < 4) {
            int m = wid * 32 + lane;
            int rid = rowids[m];
            #pragma unroll
            for (int c = 0; c < 64; c += 32) {
                unsigned rg[32], ru[32];
                ldtm32(rg, tmem_d + c);
                ldtm32(ru, tmem_d + 64 + c);
                tm_wait_ld();
                if (rid >= 0) {
                    float* dst = g_i + (size_t)rid * NI + n0g + c;
                    #pragma unroll
                    for (int j = 0; j < 32; j += 4) {
                        float4 v;
                        v.x = silu_mul(__uint_as_float(rg[j]),   __uint_as_float(ru[j]));
                        v.y = silu_mul(__uint_as_float(rg[j+1]), __uint_as_float(ru[j+1]));
                        v.z = silu_mul(__uint_as_float(rg[j+2]), __uint_as_float(ru[j+2]));
                        v.w = silu_mul(__uint_as_float(rg[j+3]), __uint_as_float(ru[j+3]));
                        *(float4*)(dst + j) = cvt4(v);
                    }
                }
            }
        }
    } else {
        // scaled atomicAdd epilogue (all 8 warps)
        int m = (wid & 3) * 32 + lane;
        int rid = rowids[m];
        int colg = (wid >> 2) * 64;
        #pragma unroll
        for (int hf = 0; hf < 2; hf++) {
            unsigned r[32];
            ldtm32(r, tmem_d + colg + hf * 32);
            tm_wait_ld();
            if (rid >= 0) {
                float g = g_gw[rid];
                float* dst = Carg + (size_t)(rid >> 1) * NH + n0 + colg + hf * 32;
                #pragma unroll
                for (int c = 0; c < 32; c++)
                    atomicAdd(dst + c, g * __uint_as_float(r[c]));
            }
        }
    }
    __syncthreads();
    if (wid == 0) tm_dealloc(tmem_d, TM_COLS);

#else
    // ================= wmma tf32 fallback =================
    __syncthreads();
    int warp = tid >> 5;
    int wm = warp & 1;
    int wn = warp >> 1;

    wmma::fragment<wmma::accumulator, 16, 16, 8, float> acc[4][2];
    #pragma unroll
    for (int fm = 0; fm < 4; fm++)
        #pragma unroll
        for (int fn = 0; fn < 2; fn++)
            wmma::fill_fragment(acc[fm][fn], 0.f);

    int lr = tid >> 2, lq = tid & 3;
    int r0 = rowids[lr], r1 = rowids[lr + 64];
    bool v0 = (r0 >= 0), v1 = (r1 >= 0);
    size_t ar0 = (size_t)(v0 ? ((MODE == 1) ? (r0 >> 1) : r0) : 0) * K;
    size_t ar1 = (size_t)(v1 ? ((MODE == 1) ? (r1 >> 1) : r1) : 0) * K;
    const float4 zero4 = make_float4(0.f, 0.f, 0.f, 0.f);
    float* As = smem;
    float* Bs = smem + BM * KPAD;

    // B row mapping (same pairing as tcgen05 path for MODE 1)
    int brow0 = (MODE == 1) ? ((lr < 64) ? (n0g + lr) : (NI + n0g + lr - 64)) : (n0 + lr);
    int brow1 = (MODE == 1) ? (NI + n0g + lr) : (n0 + lr + 64);   // lr+64 always in up-half for MODE1

    for (int kb = 0; kb < K; kb += FBK) {
        float4 av0 = v0 ? *(const float4*)(A + ar0 + kb + lq * 4) : zero4;
        float4 av1 = v1 ? *(const float4*)(A + ar1 + kb + lq * 4) : zero4;
        float4 bv0 = *(const float4*)(Bexp + (size_t)brow0 * K + kb + lq * 4);
        float4 bv1 = *(const float4*)(Bexp + (size_t)brow1 * K + kb + lq * 4);
        *(float4*)(As + lr * KPAD + lq * 4) = av0;
        *(float4*)(As + (lr + 64) * KPAD + lq * 4) = av1;
        *(float4*)(Bs + lr * KPAD + lq * 4) = bv0;
        *(float4*)(Bs + (lr + 64) * KPAD + lq * 4) = bv1;
        __syncthreads();

        #pragma unroll
        for (int kk = 0; kk < FBK; kk += 8) {
            wmma::fragment<wmma::matrix_a, 16, 16, 8, wmma::precision::tf32, wmma::row_major> af[4];
            wmma::fragment<wmma::matrix_b, 16, 16, 8, wmma::precision::tf32, wmma::col_major> bf[2];
            #pragma unroll
            for (int fm = 0; fm < 4; fm++) {
                wmma::load_matrix_sync(af[fm], As + (wm * 64 + fm * 16) * KPAD + kk, KPAD);
                #pragma unroll
                for (int u = 0; u < af[fm].num_elements; u++)
                    af[fm].x[u] = wmma::__float_to_tf32(af[fm].x[u]);
            }
            #pragma unroll
            for (int fn = 0; fn < 2; fn++) {
                wmma::load_matrix_sync(bf[fn], Bs + (wn * 32 + fn * 16) * KPAD + kk, KPAD);
                #pragma unroll
                for (int u = 0; u < bf[fn].num_elements; u++)
                    bf[fn].x[u] = wmma::__float_to_tf32(bf[fn].x[u]);
            }
            #pragma unroll
            for (int fm = 0; fm < 4; fm++)
                #pragma unroll
                for (int fn = 0; fn < 2; fn++)
                    wmma::mma_sync(acc[fm][fn], af[fm], bf[fn], acc[fm][fn]);
        }
        __syncthreads();
    }

    float* Cs = smem;
    #pragma unroll
    for (int fm = 0; fm < 4; fm++)
        #pragma unroll
        for (int fn = 0; fn < 2; fn++)
            wmma::store_matrix_sync(Cs + (size_t)(wm * 64 + fm * 16) * CLD + wn * 32 + fn * 16,
                                    acc[fm][fn], CLD, wmma::mem_row_major);
    __syncthreads();

    int r = tid >> 1;
    int rid = rowids[r];
    if (MODE == 1) {
        int j0 = (tid & 1) * 32;
        if (rid >= 0) {
            const float* src = Cs + (size_t)r * CLD;
            float* dst = g_i + (size_t)rid * NI + n0g + j0;
            #pragma unroll
            for (int j = 0; j < 32; j += 4) {
                float4 v;
                v.x = silu_mul(src[j0 + j],     src[64 + j0 + j]);
                v.y = silu_mul(src[j0 + j + 1], src[64 + j0 + j + 1]);
                v.z = silu_mul(src[j0 + j + 2], src[64 + j0 + j + 2]);
                v.w = silu_mul(src[j0 + j + 3], src[64 + j0 + j + 3]);
                *(float4*)(dst + j) = cvt4(v);
            }
        }
    } else {
        int ch = (tid & 1) * 64;
        if (rid >= 0) {
            const float* src = Cs + (size_t)r * CLD + ch;
            float g = g_gw[rid];
            float* dst = Carg + (size_t)(rid >> 1) * NH + n0 + ch;
            #pragma unroll
            for (int c = 0; c < 64; c++)
                atomicAdd(dst + c, g * src[c]);
        }
    }
#endif
}

// ---------------- launch ----------------
extern "C" void kernel_launch(void* const* d_in, const int* in_sizes, int n_in,
                              void* d_out, int out_size) {
    const float* x     = (const float*)d_in[0];
    const float* gatew = (const float*)d_in[1];
    const float* ws    = (const float*)d_in[2];
    const float* w2s   = (const float*)d_in[3];
    float* out = (float*)d_out;

    cudaFuncSetAttribute((const void*)k_gemm<1>, cudaFuncAttributeMaxDynamicSharedMemorySize, SMEM_BYTES);
    cudaFuncSetAttribute((const void*)k_gemm<2>, cudaFuncAttributeMaxDynamicSharedMemorySize, SMEM_BYTES);

    cudaMemsetAsync(d_out, 0, (size_t)out_size * sizeof(float), 0);
    k_zero_cnt<<<1, 32>>>();
    k_round_x<<<(int)(((size_t)NT * NH / 4 + 255) / 256), 256>>>(x);
    k_router<<<NT, 256>>>(x, gatew);
    // launch #5 (incl. memset) = k_gemm<1> -> ncu -s 5 profiles it

    dim3 g1(NT / BM, NI / 64, NE);            // n-block = 64 gate cols + paired up rows
    k_gemm<1><<<g1, 256, SMEM_BYTES>>>(nullptr, ws, nullptr);

    dim3 g2(NT / BM, NH / BN, NE);
    k_gemm<2><<<g2, 256, SMEM_BYTES>>>(nullptr, w2s, out);
}